// round 1
// baseline (speedup 1.0000x reference)
#include <cuda_runtime.h>

// BahadanauAttention (cosine-score attention, single query):
//   dots[s]   = keys[s] . q
//   score[s]  = dots[s] / (|q| * |keys[s]|)
//   out[h]    = sum_s score[s] * keys[s][h]
//
// Single streaming pass over keys (128 MB): each warp owns a strided set of
// rows, computes dot+sumsq via warp shuffle, and accumulates score*row into a
// register-resident 1024-float accumulator (8 x float4 per lane). Partials go
// to a __device__ scratch array; stage2 reduces them deterministically.

#define NBLK 148
#define NTHR 256
#define NWARPS (NBLK * NTHR / 32)  // 1184
#define H 1024
#define HV4 (H / 4)                // 256 float4 per row

__device__ float4 g_partial[NWARPS][HV4];   // 4.85 MB scratch

__global__ __launch_bounds__(NTHR, 1)
void bahdanau_stage1(const float* __restrict__ q,
                     const float* __restrict__ keys, int S) {
    const int warp = (blockIdx.x * NTHR + threadIdx.x) >> 5;
    const int lane = threadIdx.x & 31;

    // Load q slice for this lane: cols (i*32+lane)*4 .. +3, and q norm.
    const float4* q4 = (const float4*)q;
    float4 qv[8];
    float qss = 0.f;
#pragma unroll
    for (int i = 0; i < 8; i++) {
        qv[i] = q4[i * 32 + lane];
        qss += qv[i].x * qv[i].x + qv[i].y * qv[i].y +
               qv[i].z * qv[i].z + qv[i].w * qv[i].w;
    }
#pragma unroll
    for (int o = 16; o; o >>= 1) qss += __shfl_xor_sync(0xffffffffu, qss, o);
    const float inv_qn = rsqrtf(qss);

    float4 acc[8];
#pragma unroll
    for (int i = 0; i < 8; i++) acc[i] = make_float4(0.f, 0.f, 0.f, 0.f);

    for (int s = warp; s < S; s += NWARPS) {
        const float4* row = (const float4*)(keys + (size_t)s * H);
        float4 kv[8];
        float dot = 0.f, kss = 0.f;
#pragma unroll
        for (int i = 0; i < 8; i++) {
            kv[i] = row[i * 32 + lane];
            dot += kv[i].x * qv[i].x + kv[i].y * qv[i].y +
                   kv[i].z * qv[i].z + kv[i].w * qv[i].w;
            kss += kv[i].x * kv[i].x + kv[i].y * kv[i].y +
                   kv[i].z * kv[i].z + kv[i].w * kv[i].w;
        }
#pragma unroll
        for (int o = 16; o; o >>= 1) {
            dot += __shfl_xor_sync(0xffffffffu, dot, o);
            kss += __shfl_xor_sync(0xffffffffu, kss, o);
        }
        const float score = dot * inv_qn * rsqrtf(kss);
#pragma unroll
        for (int i = 0; i < 8; i++) {
            acc[i].x += score * kv[i].x;
            acc[i].y += score * kv[i].y;
            acc[i].z += score * kv[i].z;
            acc[i].w += score * kv[i].w;
        }
    }

#pragma unroll
    for (int i = 0; i < 8; i++) g_partial[warp][i * 32 + lane] = acc[i];
}

// Deterministic reduction of NWARPS partials. Block b handles 8 columns
// [b*8, b*8+8); tid = pg*8 + c with 32 p-groups striding over partials.
__global__ __launch_bounds__(256)
void bahdanau_stage2(float* __restrict__ out) {
    const int c  = blockIdx.x * 8 + (threadIdx.x & 7);
    const int pg = threadIdx.x >> 3;  // 0..31
    const float* part = (const float*)g_partial;

    float s = 0.f;
    for (int p = pg; p < NWARPS; p += 32)
        s += part[(size_t)p * H + c];

    __shared__ float sh[256];
    sh[threadIdx.x] = s;
    __syncthreads();
#pragma unroll
    for (int stride = 128; stride >= 8; stride >>= 1) {
        if (threadIdx.x < stride) sh[threadIdx.x] += sh[threadIdx.x + stride];
        __syncthreads();
    }
    if (threadIdx.x < 8) out[blockIdx.x * 8 + threadIdx.x] = sh[threadIdx.x];
}

extern "C" void kernel_launch(void* const* d_in, const int* in_sizes, int n_in,
                              void* d_out, int out_size) {
    const float* q    = (const float*)d_in[0];   // [1, 1024]
    const float* keys = (const float*)d_in[1];   // [S, 1024]
    const int S = in_sizes[1] / H;

    bahdanau_stage1<<<NBLK, NTHR>>>(q, keys, S);
    bahdanau_stage2<<<H / 8, 256>>>((float*)d_out);
}

// round 2
// speedup vs baseline: 1.2821x; 1.2821x over previous
#include <cuda_runtime.h>

// Fused cosine-score attention, single query.
// stage1: one streaming pass over keys (128 MB). Each warp owns strided rows,
//   computes dot(q,k) and |k|^2 via warp shuffles, accumulates score*k into a
//   register-resident 1024-float accumulator (8 x float4 per lane). Then a
//   block-level smem tree reduction collapses 16 warp partials -> 1 block
//   partial (4 KB) written to __device__ scratch.
// stage2: reduce 148 block partials (606 KB) deterministically.

#define NBLK 148
#define NTHR 512
#define WPB  (NTHR / 32)           // 16 warps per block
#define NWARPS (NBLK * WPB)        // 2368
#define H 1024
#define HV4 (H / 4)                // 256 float4 per row

__device__ float4 g_partial[NBLK][HV4];   // 148 * 4KB = 606 KB scratch

__global__ __launch_bounds__(NTHR, 1)
void bahdanau_stage1(const float* __restrict__ q,
                     const float* __restrict__ keys, int S) {
    const int wib  = threadIdx.x >> 5;                      // warp in block
    const int warp = blockIdx.x * WPB + wib;                // global warp
    const int lane = threadIdx.x & 31;

    __shared__ float4 red[8][HV4];   // 32 KB, reused across reduction phases

    // q slice for this lane + |q|
    const float4* q4 = (const float4*)q;
    float4 qv[8];
    float qss = 0.f;
#pragma unroll
    for (int i = 0; i < 8; i++) {
        qv[i] = q4[i * 32 + lane];
        qss += qv[i].x * qv[i].x + qv[i].y * qv[i].y +
               qv[i].z * qv[i].z + qv[i].w * qv[i].w;
    }
#pragma unroll
    for (int o = 16; o; o >>= 1) qss += __shfl_xor_sync(0xffffffffu, qss, o);
    const float inv_qn = rsqrtf(qss);

    float4 acc[8];
#pragma unroll
    for (int i = 0; i < 8; i++) acc[i] = make_float4(0.f, 0.f, 0.f, 0.f);

    for (int s = warp; s < S; s += NWARPS) {
        const float4* row = (const float4*)(keys + (size_t)s * H);
        float4 kv[8];
        float dot = 0.f, kss = 0.f;
#pragma unroll
        for (int i = 0; i < 8; i++) {
            kv[i] = row[i * 32 + lane];
            dot += kv[i].x * qv[i].x + kv[i].y * qv[i].y +
                   kv[i].z * qv[i].z + kv[i].w * qv[i].w;
            kss += kv[i].x * kv[i].x + kv[i].y * kv[i].y +
                   kv[i].z * kv[i].z + kv[i].w * kv[i].w;
        }
#pragma unroll
        for (int o = 16; o; o >>= 1) {
            dot += __shfl_xor_sync(0xffffffffu, dot, o);
            kss += __shfl_xor_sync(0xffffffffu, kss, o);
        }
        const float score = dot * inv_qn * rsqrtf(kss);
#pragma unroll
        for (int i = 0; i < 8; i++) {
            acc[i].x += score * kv[i].x;
            acc[i].y += score * kv[i].y;
            acc[i].z += score * kv[i].z;
            acc[i].w += score * kv[i].w;
        }
    }

    // Block tree reduction: 16 -> 8 -> 4 -> 2 -> 1 warps.
#pragma unroll
    for (int half = 8; half >= 1; half >>= 1) {
        if (wib >= half && wib < 2 * half) {
#pragma unroll
            for (int i = 0; i < 8; i++)
                red[wib - half][i * 32 + lane] = acc[i];
        }
        __syncthreads();
        if (wib < half) {
#pragma unroll
            for (int i = 0; i < 8; i++) {
                float4 v = red[wib][i * 32 + lane];
                acc[i].x += v.x; acc[i].y += v.y;
                acc[i].z += v.z; acc[i].w += v.w;
            }
        }
        __syncthreads();
    }

    if (wib == 0) {
#pragma unroll
        for (int i = 0; i < 8; i++)
            g_partial[blockIdx.x][i * 32 + lane] = acc[i];
    }
}

// stage2: out[h] = sum_{b<148} g_partial[b][h].
// 16 blocks x 512 threads; block owns 64 columns, 8 row-groups per column.
__global__ __launch_bounds__(512)
void bahdanau_stage2(float* __restrict__ out) {
    const int col = blockIdx.x * 64 + (threadIdx.x & 63);
    const int g   = threadIdx.x >> 6;   // 0..7
    const float* part = (const float*)g_partial;

    float s = 0.f;
#pragma unroll
    for (int b = 0; b < 19; b++) {      // 19*8 = 152 >= 148
        int p = g + b * 8;
        if (p < NBLK) s += part[(size_t)p * H + col];
    }

    __shared__ float sh[512];
    sh[threadIdx.x] = s;
    __syncthreads();
#pragma unroll
    for (int stride = 256; stride >= 64; stride >>= 1) {
        if (threadIdx.x < stride) sh[threadIdx.x] += sh[threadIdx.x + stride];
        __syncthreads();
    }
    if (threadIdx.x < 64) out[blockIdx.x * 64 + threadIdx.x] = sh[threadIdx.x];
}

extern "C" void kernel_launch(void* const* d_in, const int* in_sizes, int n_in,
                              void* d_out, int out_size) {
    const float* q    = (const float*)d_in[0];   // [1, 1024]
    const float* keys = (const float*)d_in[1];   // [S, 1024]
    const int S = in_sizes[1] / H;

    bahdanau_stage1<<<NBLK, NTHR>>>(q, keys, S);
    bahdanau_stage2<<<16, 512>>>((float*)d_out);
}